// round 10
// baseline (speedup 1.0000x reference)
#include <cuda_runtime.h>
#include <cuda_fp16.h>
#include <cstdint>

#define BATCH 8
#define HEADS 16
#define NTOK  1024
#define DHEAD 64
#define EMB   1024
#define KD    1024

// ---- scratch (allocation-free rule: __device__ globals) ----
// q split into fp16 hi/lo limbs; k, v single fp16. layout [b,h,n,d]
__device__ __half g_qh[BATCH*HEADS*NTOK*DHEAD];
__device__ __half g_ql[BATCH*HEADS*NTOK*DHEAD];
__device__ __half g_k [BATCH*HEADS*NTOK*DHEAD];
__device__ __half g_v [BATCH*HEADS*NTOK*DHEAD];

__device__ __half g_xh [8192*1024];   // x limbs (A side of QKV gemm)
__device__ __half g_xl [8192*1024];
__device__ __half g_wq [3072*1024];   // Wqkv single fp16 (B side)
__device__ __half g_wo [1024*1024];   // Wout single fp16
__device__ __half g_aoh[8192*1024];   // attn-out limbs (A side of out-proj)
__device__ __half g_aol[8192*1024];

// ---------------------------------------------------------------------------
__device__ __forceinline__ uint32_t smem_u32(const void* p) {
    return (uint32_t)__cvta_generic_to_shared(p);
}
__device__ __forceinline__ uint32_t pack2h(float x, float y) {
    __half2 t = __floats2half2_rn(x, y);
    return *reinterpret_cast<uint32_t*>(&t);
}
__device__ __forceinline__ void split2h(float x, float y, uint32_t& hi, uint32_t& lo) {
    __half hx = __float2half_rn(x), hy = __float2half_rn(y);
    __half2 h = __halves2half2(hx, hy);
    hi = *reinterpret_cast<uint32_t*>(&h);
    lo = pack2h(x - __half2float(hx), y - __half2float(hy));
}
__device__ __forceinline__ void ldsm_x4(uint32_t* r, uint32_t addr) {
    asm volatile("ldmatrix.sync.aligned.m8n8.x4.shared.b16 {%0,%1,%2,%3},[%4];"
                 : "=r"(r[0]), "=r"(r[1]), "=r"(r[2]), "=r"(r[3]) : "r"(addr));
}
__device__ __forceinline__ void ldsm_x4_t(uint32_t* r, uint32_t addr) {
    asm volatile("ldmatrix.sync.aligned.m8n8.x4.trans.shared.b16 {%0,%1,%2,%3},[%4];"
                 : "=r"(r[0]), "=r"(r[1]), "=r"(r[2]), "=r"(r[3]) : "r"(addr));
}
// fp32-accumulate HMMA
__device__ __forceinline__ void mma_f16(float* c, const uint32_t* a, const uint32_t* b) {
    asm volatile("mma.sync.aligned.m16n8k16.row.col.f32.f16.f16.f32 "
                 "{%0,%1,%2,%3},{%4,%5,%6,%7},{%8,%9},{%0,%1,%2,%3};"
                 : "+f"(c[0]), "+f"(c[1]), "+f"(c[2]), "+f"(c[3])
                 : "r"(a[0]), "r"(a[1]), "r"(a[2]), "r"(a[3]), "r"(b[0]), "r"(b[1]));
}
// fp16-accumulate HMMA (packed f16x2 accumulators; used for lo-limb products)
__device__ __forceinline__ void mma_f16acc(uint32_t* c, const uint32_t* a, const uint32_t* b) {
    asm volatile("mma.sync.aligned.m16n8k16.row.col.f16.f16.f16.f16 "
                 "{%0,%1},{%2,%3,%4,%5},{%6,%7},{%0,%1};"
                 : "+r"(c[0]), "+r"(c[1])
                 : "r"(a[0]), "r"(a[1]), "r"(a[2]), "r"(a[3]), "r"(b[0]), "r"(b[1]));
}
__device__ __forceinline__ void merge_lo(float* c, const uint32_t* l) {
    float2 f0 = __half22float2(*reinterpret_cast<const __half2*>(&l[0]));
    float2 f1 = __half22float2(*reinterpret_cast<const __half2*>(&l[1]));
    c[0] += f0.x; c[1] += f0.y; c[2] += f1.x; c[3] += f1.y;
}
__device__ __forceinline__ void cp16(uint32_t dst, const void* src) {
    asm volatile("cp.async.ca.shared.global [%0],[%1],16;" :: "r"(dst), "l"(src));
}
__device__ __forceinline__ void cp_commit() { asm volatile("cp.async.commit_group;"); }
__device__ __forceinline__ void cp_wait0() { asm volatile("cp.async.wait_group 0;"); }
__device__ __forceinline__ void cp_wait1() { asm volatile("cp.async.wait_group 1;"); }

// ---------------------------------------------------------------------------
// fp32 -> fp16 conversion. which 0: x -> split limbs; 1: Wqkv single; 2: Wout single
// ---------------------------------------------------------------------------
__global__ __launch_bounds__(256) void convert_kernel(const float* __restrict__ src,
                                                      int which, int n)
{
    int i = (blockIdx.x * 256 + threadIdx.x) * 4;
    if (i >= n) return;
    float4 v = *(const float4*)(src + i);
    if (which == 0) {
        uint2 ph, pl;
        split2h(v.x, v.y, ph.x, pl.x);
        split2h(v.z, v.w, ph.y, pl.y);
        *(uint2*)&g_xh[i] = ph;
        *(uint2*)&g_xl[i] = pl;
    } else {
        uint2 p;
        p.x = pack2h(v.x, v.y);
        p.y = pack2h(v.z, v.w);
        if (which == 1) *(uint2*)&g_wq[i] = p;
        else            *(uint2*)&g_wo[i] = p;
    }
}

// ---------------------------------------------------------------------------
// 2-product fp16 HMMA GEMM: C = AhB (f32-acc) + AlB (f16-acc, merged at end)
// Block 128x128, 256 thr (8 warps as 2M x 4N), warp tile 64x32, K-step 32,
// cp.async double-buffered.
// MODE 0: A=x limbs, B=Wqkv -> q limbs / k / v  (q *= 0.125)
// MODE 1: A=attn-out limbs, B=Wout -> +bias -> C (fp32)
// ---------------------------------------------------------------------------
#define GSTR 40                               // smem row stride (elems)
#define PLB  (128 * GSTR * 2)                 // plane bytes (10240)
#define BUFB (3 * PLB)                        // Ah, Al, B (30720)
#define G_SMEM_B (2 * BUFB)                   // 61440

template<int MODE>
__global__ __launch_bounds__(256, 1) void mma_gemm(const float* __restrict__ bias,
                                                   float* __restrict__ C)
{
    extern __shared__ __half gs[];

    const int t    = threadIdx.x;
    const int lane = t & 31;
    const int wid  = t >> 5;
    const int wm   = (wid & 1) << 6;       // 0 / 64
    const int wn   = (wid >> 1) << 5;      // 0..96
    const int m0   = blockIdx.y * 128;
    const int n0   = blockIdx.x * 128;

    const __half* Ah = (MODE == 0) ? g_xh : g_aoh;
    const __half* Al = (MODE == 0) ? g_xl : g_aol;
    const __half* Bp = (MODE == 0) ? g_wq : g_wo;

    const uint32_t s_base = smem_u32(gs);

#define G_LOAD(st, bf) do {                                                       \
    const int k0 = (st) * 32;                                                     \
    const uint32_t bo = s_base + (uint32_t)(bf) * BUFB;                           \
    _Pragma("unroll")                                                             \
    for (int u = 0; u < 2; u++) {                                                 \
        const int idx = t + u * 256;                                              \
        const int r = idx >> 2, c = (idx & 3) << 3;                               \
        const uint32_t so = (uint32_t)(r * GSTR + c) * 2;                         \
        const size_t ga = (size_t)(m0 + r) * KD + k0 + c;                         \
        const size_t gb = (size_t)(n0 + r) * KD + k0 + c;                         \
        cp16(bo + so,           Ah + ga);                                         \
        cp16(bo + PLB + so,     Al + ga);                                         \
        cp16(bo + 2 * PLB + so, Bp + gb);                                         \
    }                                                                             \
    cp_commit(); } while (0)

    const int a_r = wm + (lane & 15);
    const int a_c = (lane >> 4) << 3;
    const int b_r = wn + ((lane >> 4) << 3) + (lane & 7);
    const int b_c = ((lane >> 3) & 1) << 3;

    float    acc [4][4][4];
    uint32_t lacc[4][4][2];
    #pragma unroll
    for (int mt = 0; mt < 4; mt++)
        #pragma unroll
        for (int nt = 0; nt < 4; nt++) {
            #pragma unroll
            for (int q = 0; q < 4; q++) acc[mt][nt][q] = 0.f;
            lacc[mt][nt][0] = 0u; lacc[mt][nt][1] = 0u;
        }

    G_LOAD(0, 0);

    const int NSTEP = KD / 32;
    for (int st = 0; st < NSTEP; st++) {
        const int buf = st & 1;
        cp_wait0();
        __syncthreads();
        if (st + 1 < NSTEP) G_LOAD(st + 1, 1 - buf);

        const uint32_t bo = s_base + (uint32_t)buf * BUFB;
        #pragma unroll
        for (int kk = 0; kk < 32; kk += 16) {
            uint32_t ah[4][4], al[4][4], bf[2][4];
            #pragma unroll
            for (int mt = 0; mt < 4; mt++) {
                const uint32_t ad = bo + (uint32_t)(((a_r + mt * 16) * GSTR) + kk + a_c) * 2;
                ldsm_x4(ah[mt], ad);
                ldsm_x4(al[mt], ad + PLB);
            }
            #pragma unroll
            for (int pr = 0; pr < 2; pr++) {
                const uint32_t bd = bo + 2 * PLB
                    + (uint32_t)(((b_r + pr * 16) * GSTR) + kk + b_c) * 2;
                ldsm_x4(bf[pr], bd);
            }
            #pragma unroll
            for (int mt = 0; mt < 4; mt++)
                #pragma unroll
                for (int nt = 0; nt < 4; nt++) {
                    uint32_t* B0 = &bf[nt >> 1][(nt & 1) * 2];
                    mma_f16(acc[mt][nt], ah[mt], B0);
                    mma_f16acc(lacc[mt][nt], al[mt], B0);
                }
        }
        __syncthreads();
    }

    // merge lo-limb f16 accumulators
    #pragma unroll
    for (int mt = 0; mt < 4; mt++)
        #pragma unroll
        for (int nt = 0; nt < 4; nt++)
            merge_lo(acc[mt][nt], lacc[mt][nt]);

    // ---- epilogue ----
    const int part = (MODE == 0) ? (n0 >> 10) : 0;
    const int e0   = n0 & 1023;
    #pragma unroll
    for (int mt = 0; mt < 4; mt++) {
        #pragma unroll
        for (int half = 0; half < 2; half++) {
            const int m = m0 + wm + mt * 16 + (lane >> 2) + half * 8;
            if (MODE == 0) {
                const int bb = m >> 10, nn = m & 1023;
                #pragma unroll
                for (int nt = 0; nt < 4; nt++) {
                    const int e  = e0 + wn + nt * 8 + (lane & 3) * 2;
                    const int hh = e >> 6, d = e & 63;
                    const size_t off = ((size_t)((bb * HEADS + hh) * NTOK + nn) << 6) + d;
                    float vx = acc[mt][nt][half * 2], vy = acc[mt][nt][half * 2 + 1];
                    if (part == 0) {
                        uint32_t hi, lo;
                        split2h(vx * 0.125f, vy * 0.125f, hi, lo);
                        *(uint32_t*)&g_qh[off] = hi;
                        *(uint32_t*)&g_ql[off] = lo;
                    } else if (part == 1) {
                        *(uint32_t*)&g_k[off] = pack2h(vx, vy);
                    } else {
                        *(uint32_t*)&g_v[off] = pack2h(vx, vy);
                    }
                }
            } else {
                #pragma unroll
                for (int nt = 0; nt < 4; nt++) {
                    const int cg = n0 + wn + nt * 8 + (lane & 3) * 2;
                    const float2 b2 = *(const float2*)&bias[cg];
                    float2 v = make_float2(acc[mt][nt][half * 2] + b2.x,
                                           acc[mt][nt][half * 2 + 1] + b2.y);
                    *(float2*)&C[(size_t)m * EMB + cg] = v;
                }
            }
        }
    }
}

// ============================================================================
// fp16 2-product flash attention; lo-limb products use f16 accumulators.
// Block = 128 queries (8 warps x m16), 16 key tiles of 64.
// smem: [2 bufs][K plane, V plane][64 rows][72 fp16] + bias[1024] f32
// ============================================================================
#define ASTR 72
#define PLNB (64 * ASTR * 2)                  // plane bytes (9216)
#define ATTN_SMEM (2 * 2 * PLNB + 1024 * 4)   // 40960

__global__ __launch_bounds__(256) void attn_mma(const float* __restrict__ biases)
{
    extern __shared__ __half smem[];
    float* s_bias = (float*)((char*)smem + 2 * 2 * PLNB);

    const int t = threadIdx.x, lane = t & 31, w = t >> 5;
    const int qt = blockIdx.x, h = blockIdx.y, b = blockIdx.z;
    const int bh = b * HEADS + h;
    const int q0 = qt * 128;
    const int rw = w * 16;

    for (int i = t; i < 1024; i += 256) s_bias[i] = biases[h * 1024 + i];

    // ---- Q fragment preload (hi, lo limbs), staged through smem ----
    uint32_t qh[4][4], ql[4][4];
    const uint32_t qAddr = smem_u32(smem) + ((rw + (lane & 15)) * ASTR + ((lane >> 4) << 3)) * 2;
    {
        const __half* qsrc = g_qh + ((size_t)bh * NTOK + q0) * 64;
        #pragma unroll
        for (int u = 0; u < 4; u++) {
            const int id = t + u * 256, r = id >> 3, ch = (id & 7) * 8;
            cp16(smem_u32(smem + r * ASTR + ch), qsrc + (size_t)r * 64 + ch);
        }
        cp_commit(); cp_wait0(); __syncthreads();
        #pragma unroll
        for (int kk = 0; kk < 4; kk++) ldsm_x4(qh[kk], qAddr + kk * 32);
        __syncthreads();

        qsrc = g_ql + ((size_t)bh * NTOK + q0) * 64;
        #pragma unroll
        for (int u = 0; u < 4; u++) {
            const int id = t + u * 256, r = id >> 3, ch = (id & 7) * 8;
            cp16(smem_u32(smem + r * ASTR + ch), qsrc + (size_t)r * 64 + ch);
        }
        cp_commit(); cp_wait0(); __syncthreads();
        #pragma unroll
        for (int kk = 0; kk < 4; kk++) ldsm_x4(ql[kk], qAddr + kk * 32);
        __syncthreads();
    }

    float s[8][4], o[8][4];
    float m0 = -1e30f, m1 = -1e30f, l0 = 0.f, l1 = 0.f;
    #pragma unroll
    for (int f = 0; f < 8; f++)
        #pragma unroll
        for (int q = 0; q < 4; q++) o[f][q] = 0.f;

    const int r_row0 = q0 + rw + (lane >> 2);
    const int xq0 = r_row0 >> 5,       yq0 = r_row0 & 31;
    const int xq1 = (r_row0 + 8) >> 5, yq1 = (r_row0 + 8) & 31;

#define LOAD_TILE(kt, bf) do {                                                   \
    _Pragma("unroll")                                                            \
    for (int u = 0; u < 4; u++) {                                                \
        const int p = u >> 1;                                                    \
        const int id = t + u * 256;                                              \
        const int rr = (id >> 3) & 63, ch = (id & 7) * 8;                        \
        const __half* src = (p == 0) ? g_k : g_v;                                \
        cp16(smem_u32(smem + (((bf) * 2 + p) * 64 + rr) * ASTR + ch),            \
             src + ((size_t)bh * NTOK + (kt) * 64 + rr) * 64 + ch);              \
    }                                                                            \
    cp_commit(); } while (0)

    LOAD_TILE(0, 0);

    for (int kt = 0; kt < 16; kt++) {
        const int buf = kt & 1;
        if (kt < 15) { LOAD_TILE(kt + 1, 1 - buf); cp_wait1(); }
        else         { cp_wait0(); }
        __syncthreads();

        const uint32_t base = smem_u32(smem) + buf * 2 * PLNB;
        const uint32_t laddr = ((lane & 15) * ASTR + ((lane >> 4) << 3)) * 2;

        // ---- S = Qh K (f32-acc) + Ql K (f16-acc) ----
        #pragma unroll
        for (int f = 0; f < 8; f++)
            #pragma unroll
            for (int q = 0; q < 4; q++) s[f][q] = 0.f;
        uint32_t ls[8][2];
        #pragma unroll
        for (int f = 0; f < 8; f++) { ls[f][0] = 0u; ls[f][1] = 0u; }

        #pragma unroll
        for (int kk = 0; kk < 4; kk++) {
            #pragma unroll
            for (int ng = 0; ng < 4; ng++) {
                uint32_t kf[4];
                ldsm_x4(kf, base + laddr + (ng * 16 * ASTR + kk * 16) * 2);
                uint32_t b0[2] = {kf[0], kf[2]}, b1[2] = {kf[1], kf[3]};
                mma_f16(s[2*ng],   qh[kk], b0);
                mma_f16acc(ls[2*ng],   ql[kk], b0);
                mma_f16(s[2*ng+1], qh[kk], b1);
                mma_f16acc(ls[2*ng+1], ql[kk], b1);
            }
        }
        #pragma unroll
        for (int f = 0; f < 8; f++) merge_lo(s[f], ls[f]);

        // ---- bias + online softmax ----
        float tm0 = -1e30f, tm1 = -1e30f;
        const int cb = kt * 64 + (lane & 3) * 2;
        #pragma unroll
        for (int f = 0; f < 8; f++) {
            const int c0 = cb + f * 8, c1 = c0 + 1;
            const int cx0 = c0 >> 5, cy0 = c0 & 31;
            const int cx1 = c1 >> 5, cy1 = c1 & 31;
            s[f][0] += s_bias[abs(xq0 - cx0) * 32 + abs(yq0 - cy0)];
            s[f][1] += s_bias[abs(xq0 - cx1) * 32 + abs(yq0 - cy1)];
            s[f][2] += s_bias[abs(xq1 - cx0) * 32 + abs(yq1 - cy0)];
            s[f][3] += s_bias[abs(xq1 - cx1) * 32 + abs(yq1 - cy1)];
            tm0 = fmaxf(tm0, fmaxf(s[f][0], s[f][1]));
            tm1 = fmaxf(tm1, fmaxf(s[f][2], s[f][3]));
        }
        tm0 = fmaxf(tm0, __shfl_xor_sync(0xffffffffu, tm0, 1));
        tm0 = fmaxf(tm0, __shfl_xor_sync(0xffffffffu, tm0, 2));
        tm1 = fmaxf(tm1, __shfl_xor_sync(0xffffffffu, tm1, 1));
        tm1 = fmaxf(tm1, __shfl_xor_sync(0xffffffffu, tm1, 2));

        const float mn0 = fmaxf(m0, tm0), mn1 = fmaxf(m1, tm1);
        const float fac0 = __expf(m0 - mn0), fac1 = __expf(m1 - mn1);
        m0 = mn0; m1 = mn1;
        l0 *= fac0; l1 *= fac1;
        #pragma unroll
        for (int f = 0; f < 8; f++) {
            s[f][0] = __expf(s[f][0] - m0); s[f][1] = __expf(s[f][1] - m0);
            s[f][2] = __expf(s[f][2] - m1); s[f][3] = __expf(s[f][3] - m1);
            l0 += s[f][0] + s[f][1];
            l1 += s[f][2] + s[f][3];
            o[f][0] *= fac0; o[f][1] *= fac0; o[f][2] *= fac1; o[f][3] *= fac1;
        }

        // ---- O += Ph V (f32-acc) + Pl V (f16-acc) ----
        uint32_t lv[8][2];
        #pragma unroll
        for (int f = 0; f < 8; f++) { lv[f][0] = 0u; lv[f][1] = 0u; }

        const uint32_t vbase = base + PLNB;
        #pragma unroll
        for (int kk2 = 0; kk2 < 4; kk2++) {
            uint32_t ah[4], al[4];
            split2h(s[2*kk2][0],   s[2*kk2][1],   ah[0], al[0]);
            split2h(s[2*kk2][2],   s[2*kk2][3],   ah[1], al[1]);
            split2h(s[2*kk2+1][0], s[2*kk2+1][1], ah[2], al[2]);
            split2h(s[2*kk2+1][2], s[2*kk2+1][3], ah[3], al[3]);
            #pragma unroll
            for (int dg = 0; dg < 4; dg++) {
                const int nf = dg * 2;
                uint32_t vf[4];
                ldsm_x4_t(vf, vbase + laddr + (kk2 * 16 * ASTR + dg * 16) * 2);
                uint32_t b0[2] = {vf[0], vf[1]}, b1[2] = {vf[2], vf[3]};
                mma_f16(o[nf],   ah, b0);
                mma_f16acc(lv[nf],   al, b0);
                mma_f16(o[nf+1], ah, b1);
                mma_f16acc(lv[nf+1], al, b1);
            }
        }
        #pragma unroll
        for (int f = 0; f < 8; f++) merge_lo(o[f], lv[f]);
        __syncthreads();
    }

    // ---- epilogue: normalize, write attn-out fp16 limbs ----
    l0 += __shfl_xor_sync(0xffffffffu, l0, 1);
    l0 += __shfl_xor_sync(0xffffffffu, l0, 2);
    l1 += __shfl_xor_sync(0xffffffffu, l1, 1);
    l1 += __shfl_xor_sync(0xffffffffu, l1, 2);
    const float inv0 = 1.0f / l0, inv1 = 1.0f / l1;

    const size_t rbase0 = ((size_t)(b * NTOK + r_row0)) * EMB + h * 64;
    const size_t rbase1 = rbase0 + (size_t)8 * EMB;
    #pragma unroll
    for (int f = 0; f < 8; f++) {
        const int d = f * 8 + (lane & 3) * 2;
        uint32_t hi, lo;
        split2h(o[f][0] * inv0, o[f][1] * inv0, hi, lo);
        *(uint32_t*)&g_aoh[rbase0 + d] = hi;
        *(uint32_t*)&g_aol[rbase0 + d] = lo;
        split2h(o[f][2] * inv1, o[f][3] * inv1, hi, lo);
        *(uint32_t*)&g_aoh[rbase1 + d] = hi;
        *(uint32_t*)&g_aol[rbase1 + d] = lo;
    }
}

// ============================================================================
extern "C" void kernel_launch(void* const* d_in, const int* in_sizes, int n_in,
                              void* d_out, int out_size)
{
    const float* x     = (const float*)d_in[0];
    const float* Wqkv  = (const float*)d_in[1];
    const float* ab    = (const float*)d_in[2];
    // d_in[3] = bias_idxs : not needed (idx = |dx|*32 + |dy| analytically)
    const float* Wout  = (const float*)d_in[4];
    const float* bout  = (const float*)d_in[5];
    float* out = (float*)d_out;

    cudaFuncSetAttribute(attn_mma, cudaFuncAttributeMaxDynamicSharedMemorySize,
                         ATTN_SMEM);
    cudaFuncSetAttribute(mma_gemm<0>, cudaFuncAttributeMaxDynamicSharedMemorySize,
                         G_SMEM_B);
    cudaFuncSetAttribute(mma_gemm<1>, cudaFuncAttributeMaxDynamicSharedMemorySize,
                         G_SMEM_B);

    convert_kernel<<<8192*1024/1024, 256>>>(x,    0, 8192*1024);
    convert_kernel<<<3072*1024/1024, 256>>>(Wqkv, 1, 3072*1024);
    convert_kernel<<<1024*1024/1024, 256>>>(Wout, 2, 1024*1024);

    mma_gemm<0><<<dim3(3072/128, 8192/128), 256, G_SMEM_B>>>(nullptr, nullptr);
    attn_mma<<<dim3(NTOK/128, HEADS, BATCH), 256, ATTN_SMEM>>>(ab);
    mma_gemm<1><<<dim3(1024/128, 8192/128), 256, G_SMEM_B>>>(bout, out);
}

// round 11
// speedup vs baseline: 1.6930x; 1.6930x over previous
#include <cuda_runtime.h>
#include <cuda_fp16.h>
#include <cstdint>

#define BATCH 8
#define HEADS 16
#define NTOK  1024
#define DHEAD 64
#define EMB   1024
#define KD    1024

// ---- scratch (allocation-free rule: __device__ globals) ----
// everything single fp16. layout [b,h,n,d] for q/k/v
__device__ __half g_q [BATCH*HEADS*NTOK*DHEAD];   // pre-scaled by 0.125
__device__ __half g_k [BATCH*HEADS*NTOK*DHEAD];
__device__ __half g_v [BATCH*HEADS*NTOK*DHEAD];

__device__ __half g_x [8192*1024];   // x fp16 (A side of QKV gemm)
__device__ __half g_wq[3072*1024];   // Wqkv fp16 (B side)
__device__ __half g_wo[1024*1024];   // Wout fp16
__device__ __half g_ao[8192*1024];   // attn-out fp16 (A side of out-proj)

// ---------------------------------------------------------------------------
__device__ __forceinline__ uint32_t smem_u32(const void* p) {
    return (uint32_t)__cvta_generic_to_shared(p);
}
__device__ __forceinline__ uint32_t pack2h(float x, float y) {
    __half2 t = __floats2half2_rn(x, y);
    return *reinterpret_cast<uint32_t*>(&t);
}
__device__ __forceinline__ void ldsm_x4(uint32_t* r, uint32_t addr) {
    asm volatile("ldmatrix.sync.aligned.m8n8.x4.shared.b16 {%0,%1,%2,%3},[%4];"
                 : "=r"(r[0]), "=r"(r[1]), "=r"(r[2]), "=r"(r[3]) : "r"(addr));
}
__device__ __forceinline__ void ldsm_x4_t(uint32_t* r, uint32_t addr) {
    asm volatile("ldmatrix.sync.aligned.m8n8.x4.trans.shared.b16 {%0,%1,%2,%3},[%4];"
                 : "=r"(r[0]), "=r"(r[1]), "=r"(r[2]), "=r"(r[3]) : "r"(addr));
}
__device__ __forceinline__ void mma_f16(float* c, const uint32_t* a, const uint32_t* b) {
    asm volatile("mma.sync.aligned.m16n8k16.row.col.f32.f16.f16.f32 "
                 "{%0,%1,%2,%3},{%4,%5,%6,%7},{%8,%9},{%0,%1,%2,%3};"
                 : "+f"(c[0]), "+f"(c[1]), "+f"(c[2]), "+f"(c[3])
                 : "r"(a[0]), "r"(a[1]), "r"(a[2]), "r"(a[3]), "r"(b[0]), "r"(b[1]));
}
__device__ __forceinline__ void cp16(uint32_t dst, const void* src) {
    asm volatile("cp.async.ca.shared.global [%0],[%1],16;" :: "r"(dst), "l"(src));
}
__device__ __forceinline__ void cp_commit() { asm volatile("cp.async.commit_group;"); }
__device__ __forceinline__ void cp_wait0() { asm volatile("cp.async.wait_group 0;"); }
__device__ __forceinline__ void cp_wait1() { asm volatile("cp.async.wait_group 1;"); }

// ---------------------------------------------------------------------------
// fp32 -> fp16 conversion. which 0: x; 1: Wqkv; 2: Wout
// ---------------------------------------------------------------------------
__global__ __launch_bounds__(256) void convert_kernel(const float* __restrict__ src,
                                                      int which, int n)
{
    int i = (blockIdx.x * 256 + threadIdx.x) * 4;
    if (i >= n) return;
    float4 v = *(const float4*)(src + i);
    uint2 p;
    p.x = pack2h(v.x, v.y);
    p.y = pack2h(v.z, v.w);
    if (which == 0)      *(uint2*)&g_x [i] = p;
    else if (which == 1) *(uint2*)&g_wq[i] = p;
    else                 *(uint2*)&g_wo[i] = p;
}

// ---------------------------------------------------------------------------
// Single-product fp16 HMMA GEMM: C[m,c] = A(m,:) . B(c,:)
// Block 128x256, 256 thr (8 warps as 2M x 4N), warp tile 64x64, K-step 32,
// cp.async double-buffered.
// MODE 0: A=x, B=Wqkv -> q (scaled) / k / v fp16
// MODE 1: A=attn-out, B=Wout -> +bias -> C (fp32)
// ---------------------------------------------------------------------------
#define GSTR 40                               // smem row stride (elems)
#define APLB (128 * GSTR * 2)                 // A plane bytes (10240)
#define BPLB (256 * GSTR * 2)                 // B plane bytes (20480)
#define BUFB (APLB + BPLB)                    // buffer bytes (30720)
#define G_SMEM_B (2 * BUFB)                   // 61440

template<int MODE>
__global__ __launch_bounds__(256, 1) void mma_gemm(const float* __restrict__ bias,
                                                   float* __restrict__ C)
{
    extern __shared__ __half gs[];

    const int t    = threadIdx.x;
    const int lane = t & 31;
    const int wid  = t >> 5;
    const int wm   = (wid & 1) << 6;       // 0 / 64
    const int wn   = (wid >> 1) << 6;      // 0 / 64 / 128 / 192
    const int m0   = blockIdx.y * 128;
    const int n0   = blockIdx.x * 256;

    const __half* Ap = (MODE == 0) ? g_x  : g_ao;
    const __half* Bp = (MODE == 0) ? g_wq : g_wo;

    const uint32_t s_base = smem_u32(gs);

#define G_LOAD(st, bf) do {                                                       \
    const int k0 = (st) * 32;                                                     \
    const uint32_t bo = s_base + (uint32_t)(bf) * BUFB;                           \
    _Pragma("unroll")                                                             \
    for (int u = 0; u < 2; u++) {          /* A: 128 rows x 4 chunks */           \
        const int idx = t + u * 256;                                              \
        const int r = idx >> 2, c = (idx & 3) << 3;                               \
        const uint32_t so = (uint32_t)(r * GSTR + c) * 2;                         \
        cp16(bo + so, Ap + (size_t)(m0 + r) * KD + k0 + c);                       \
    }                                                                             \
    _Pragma("unroll")                                                             \
    for (int u = 0; u < 4; u++) {          /* B: 256 rows x 4 chunks */           \
        const int idx = t + u * 256;                                              \
        const int r = idx >> 2, c = (idx & 3) << 3;                               \
        const uint32_t so = (uint32_t)(r * GSTR + c) * 2;                         \
        cp16(bo + APLB + so, Bp + (size_t)(n0 + r) * KD + k0 + c);                \
    }                                                                             \
    cp_commit(); } while (0)

    const int a_r = wm + (lane & 15);
    const int a_c = (lane >> 4) << 3;
    const int b_r = wn + ((lane >> 4) << 3) + (lane & 7);
    const int b_c = ((lane >> 3) & 1) << 3;

    float acc[4][8][4];
    #pragma unroll
    for (int mt = 0; mt < 4; mt++)
        #pragma unroll
        for (int nt = 0; nt < 8; nt++)
            #pragma unroll
            for (int q = 0; q < 4; q++) acc[mt][nt][q] = 0.f;

    G_LOAD(0, 0);

    const int NSTEP = KD / 32;
    for (int st = 0; st < NSTEP; st++) {
        const int buf = st & 1;
        cp_wait0();
        __syncthreads();
        if (st + 1 < NSTEP) G_LOAD(st + 1, 1 - buf);

        const uint32_t bo = s_base + (uint32_t)buf * BUFB;
        #pragma unroll
        for (int kk = 0; kk < 32; kk += 16) {
            uint32_t ah[4][4];
            #pragma unroll
            for (int mt = 0; mt < 4; mt++)
                ldsm_x4(ah[mt], bo + (uint32_t)(((a_r + mt * 16) * GSTR) + kk + a_c) * 2);
            #pragma unroll
            for (int half = 0; half < 2; half++) {
                uint32_t bhf[2][4];
                #pragma unroll
                for (int prl = 0; prl < 2; prl++) {
                    const int pr = half * 2 + prl;
                    ldsm_x4(bhf[prl], bo + APLB
                        + (uint32_t)(((b_r + pr * 16) * GSTR) + kk + b_c) * 2);
                }
                #pragma unroll
                for (int mt = 0; mt < 4; mt++)
                    #pragma unroll
                    for (int ntl = 0; ntl < 4; ntl++) {
                        uint32_t* B0 = &bhf[ntl >> 1][(ntl & 1) * 2];
                        mma_f16(acc[mt][half * 4 + ntl], ah[mt], B0);
                    }
            }
        }
        __syncthreads();
    }

    // ---- epilogue ----
    const int part = (MODE == 0) ? (n0 >> 10) : 0;
    const int e0   = n0 & 1023;
    #pragma unroll
    for (int mt = 0; mt < 4; mt++) {
        #pragma unroll
        for (int half = 0; half < 2; half++) {
            const int m = m0 + wm + mt * 16 + (lane >> 2) + half * 8;
            if (MODE == 0) {
                const int bb = m >> 10, nn = m & 1023;
                #pragma unroll
                for (int nt = 0; nt < 8; nt++) {
                    const int e  = e0 + wn + nt * 8 + (lane & 3) * 2;
                    const int hh = e >> 6, d = e & 63;
                    const size_t off = ((size_t)((bb * HEADS + hh) * NTOK + nn) << 6) + d;
                    float vx = acc[mt][nt][half * 2], vy = acc[mt][nt][half * 2 + 1];
                    if (part == 0) {
                        *(uint32_t*)&g_q[off] = pack2h(vx * 0.125f, vy * 0.125f);
                    } else if (part == 1) {
                        *(uint32_t*)&g_k[off] = pack2h(vx, vy);
                    } else {
                        *(uint32_t*)&g_v[off] = pack2h(vx, vy);
                    }
                }
            } else {
                #pragma unroll
                for (int nt = 0; nt < 8; nt++) {
                    const int cg = n0 + wn + nt * 8 + (lane & 3) * 2;
                    const float2 b2 = *(const float2*)&bias[cg];
                    float2 v = make_float2(acc[mt][nt][half * 2] + b2.x,
                                           acc[mt][nt][half * 2 + 1] + b2.y);
                    *(float2*)&C[(size_t)m * EMB + cg] = v;
                }
            }
        }
    }
}

// ============================================================================
// Single-product fp16 flash attention.
// Block = 128 queries (8 warps x m16), 16 key tiles of 64.
// smem: [2 bufs][K plane, V plane][64 rows][72 fp16] + bias[1024] f32
// ============================================================================
#define ASTR 72
#define PLNB (64 * ASTR * 2)                  // plane bytes (9216)
#define ATTN_SMEM (2 * 2 * PLNB + 1024 * 4)   // 40960

__global__ __launch_bounds__(256) void attn_mma(const float* __restrict__ biases)
{
    extern __shared__ __half smem[];
    float* s_bias = (float*)((char*)smem + 2 * 2 * PLNB);

    const int t = threadIdx.x, lane = t & 31, w = t >> 5;
    const int qt = blockIdx.x, h = blockIdx.y, b = blockIdx.z;
    const int bh = b * HEADS + h;
    const int q0 = qt * 128;
    const int rw = w * 16;

    for (int i = t; i < 1024; i += 256) s_bias[i] = biases[h * 1024 + i];

    // ---- Q fragment preload, staged through smem ----
    uint32_t qf[4][4];
    const uint32_t qAddr = smem_u32(smem) + ((rw + (lane & 15)) * ASTR + ((lane >> 4) << 3)) * 2;
    {
        const __half* qsrc = g_q + ((size_t)bh * NTOK + q0) * 64;
        #pragma unroll
        for (int u = 0; u < 4; u++) {
            const int id = t + u * 256, r = id >> 3, ch = (id & 7) * 8;
            cp16(smem_u32(smem + r * ASTR + ch), qsrc + (size_t)r * 64 + ch);
        }
        cp_commit(); cp_wait0(); __syncthreads();
        #pragma unroll
        for (int kk = 0; kk < 4; kk++) ldsm_x4(qf[kk], qAddr + kk * 32);
        __syncthreads();
    }

    float s[8][4], o[8][4];
    float m0 = -1e30f, m1 = -1e30f, l0 = 0.f, l1 = 0.f;
    #pragma unroll
    for (int f = 0; f < 8; f++)
        #pragma unroll
        for (int q = 0; q < 4; q++) o[f][q] = 0.f;

    const int r_row0 = q0 + rw + (lane >> 2);
    const int xq0 = r_row0 >> 5,       yq0 = r_row0 & 31;
    const int xq1 = (r_row0 + 8) >> 5, yq1 = (r_row0 + 8) & 31;

#define LOAD_TILE(kt, bf) do {                                                   \
    _Pragma("unroll")                                                            \
    for (int u = 0; u < 4; u++) {                                                \
        const int p = u >> 1;                                                    \
        const int id = t + u * 256;                                              \
        const int rr = (id >> 3) & 63, ch = (id & 7) * 8;                        \
        const __half* src = (p == 0) ? g_k : g_v;                                \
        cp16(smem_u32(smem + (((bf) * 2 + p) * 64 + rr) * ASTR + ch),            \
             src + ((size_t)bh * NTOK + (kt) * 64 + rr) * 64 + ch);              \
    }                                                                            \
    cp_commit(); } while (0)

    LOAD_TILE(0, 0);

    for (int kt = 0; kt < 16; kt++) {
        const int buf = kt & 1;
        if (kt < 15) { LOAD_TILE(kt + 1, 1 - buf); cp_wait1(); }
        else         { cp_wait0(); }
        __syncthreads();

        const uint32_t base = smem_u32(smem) + buf * 2 * PLNB;
        const uint32_t laddr = ((lane & 15) * ASTR + ((lane >> 4) << 3)) * 2;

        // ---- S = Q K^T ----
        #pragma unroll
        for (int f = 0; f < 8; f++)
            #pragma unroll
            for (int q = 0; q < 4; q++) s[f][q] = 0.f;

        #pragma unroll
        for (int kk = 0; kk < 4; kk++) {
            #pragma unroll
            for (int ng = 0; ng < 4; ng++) {
                uint32_t kf[4];
                ldsm_x4(kf, base + laddr + (ng * 16 * ASTR + kk * 16) * 2);
                uint32_t b0[2] = {kf[0], kf[2]}, b1[2] = {kf[1], kf[3]};
                mma_f16(s[2*ng],   qf[kk], b0);
                mma_f16(s[2*ng+1], qf[kk], b1);
            }
        }

        // ---- bias + online softmax ----
        float tm0 = -1e30f, tm1 = -1e30f;
        const int cb = kt * 64 + (lane & 3) * 2;
        #pragma unroll
        for (int f = 0; f < 8; f++) {
            const int c0 = cb + f * 8, c1 = c0 + 1;
            const int cx0 = c0 >> 5, cy0 = c0 & 31;
            const int cx1 = c1 >> 5, cy1 = c1 & 31;
            s[f][0] += s_bias[abs(xq0 - cx0) * 32 + abs(yq0 - cy0)];
            s[f][1] += s_bias[abs(xq0 - cx1) * 32 + abs(yq0 - cy1)];
            s[f][2] += s_bias[abs(xq1 - cx0) * 32 + abs(yq1 - cy0)];
            s[f][3] += s_bias[abs(xq1 - cx1) * 32 + abs(yq1 - cy1)];
            tm0 = fmaxf(tm0, fmaxf(s[f][0], s[f][1]));
            tm1 = fmaxf(tm1, fmaxf(s[f][2], s[f][3]));
        }
        tm0 = fmaxf(tm0, __shfl_xor_sync(0xffffffffu, tm0, 1));
        tm0 = fmaxf(tm0, __shfl_xor_sync(0xffffffffu, tm0, 2));
        tm1 = fmaxf(tm1, __shfl_xor_sync(0xffffffffu, tm1, 1));
        tm1 = fmaxf(tm1, __shfl_xor_sync(0xffffffffu, tm1, 2));

        const float mn0 = fmaxf(m0, tm0), mn1 = fmaxf(m1, tm1);
        const float fac0 = __expf(m0 - mn0), fac1 = __expf(m1 - mn1);
        m0 = mn0; m1 = mn1;
        l0 *= fac0; l1 *= fac1;
        #pragma unroll
        for (int f = 0; f < 8; f++) {
            s[f][0] = __expf(s[f][0] - m0); s[f][1] = __expf(s[f][1] - m0);
            s[f][2] = __expf(s[f][2] - m1); s[f][3] = __expf(s[f][3] - m1);
            l0 += s[f][0] + s[f][1];
            l1 += s[f][2] + s[f][3];
            o[f][0] *= fac0; o[f][1] *= fac0; o[f][2] *= fac1; o[f][3] *= fac1;
        }

        // ---- O += P V (P packed to fp16 in-register) ----
        const uint32_t vbase = base + PLNB;
        #pragma unroll
        for (int kk2 = 0; kk2 < 4; kk2++) {
            uint32_t ap[4];
            ap[0] = pack2h(s[2*kk2][0],   s[2*kk2][1]);
            ap[1] = pack2h(s[2*kk2][2],   s[2*kk2][3]);
            ap[2] = pack2h(s[2*kk2+1][0], s[2*kk2+1][1]);
            ap[3] = pack2h(s[2*kk2+1][2], s[2*kk2+1][3]);
            #pragma unroll
            for (int dg = 0; dg < 4; dg++) {
                const int nf = dg * 2;
                uint32_t vf[4];
                ldsm_x4_t(vf, vbase + laddr + (kk2 * 16 * ASTR + dg * 16) * 2);
                uint32_t b0[2] = {vf[0], vf[1]}, b1[2] = {vf[2], vf[3]};
                mma_f16(o[nf],   ap, b0);
                mma_f16(o[nf+1], ap, b1);
            }
        }
        __syncthreads();
    }

    // ---- epilogue: normalize, write attn-out fp16 ----
    l0 += __shfl_xor_sync(0xffffffffu, l0, 1);
    l0 += __shfl_xor_sync(0xffffffffu, l0, 2);
    l1 += __shfl_xor_sync(0xffffffffu, l1, 1);
    l1 += __shfl_xor_sync(0xffffffffu, l1, 2);
    const float inv0 = 1.0f / l0, inv1 = 1.0f / l1;

    const size_t rbase0 = ((size_t)(b * NTOK + r_row0)) * EMB + h * 64;
    const size_t rbase1 = rbase0 + (size_t)8 * EMB;
    #pragma unroll
    for (int f = 0; f < 8; f++) {
        const int d = f * 8 + (lane & 3) * 2;
        *(uint32_t*)&g_ao[rbase0 + d] = pack2h(o[f][0] * inv0, o[f][1] * inv0);
        *(uint32_t*)&g_ao[rbase1 + d] = pack2h(o[f][2] * inv1, o[f][3] * inv1);
    }
}

// ============================================================================
extern "C" void kernel_launch(void* const* d_in, const int* in_sizes, int n_in,
                              void* d_out, int out_size)
{
    const float* x     = (const float*)d_in[0];
    const float* Wqkv  = (const float*)d_in[1];
    const float* ab    = (const float*)d_in[2];
    // d_in[3] = bias_idxs : not needed (idx = |dx|*32 + |dy| analytically)
    const float* Wout  = (const float*)d_in[4];
    const float* bout  = (const float*)d_in[5];
    float* out = (float*)d_out;

    cudaFuncSetAttribute(attn_mma, cudaFuncAttributeMaxDynamicSharedMemorySize,
                         ATTN_SMEM);
    cudaFuncSetAttribute(mma_gemm<0>, cudaFuncAttributeMaxDynamicSharedMemorySize,
                         G_SMEM_B);
    cudaFuncSetAttribute(mma_gemm<1>, cudaFuncAttributeMaxDynamicSharedMemorySize,
                         G_SMEM_B);

    convert_kernel<<<8192*1024/1024, 256>>>(x,    0, 8192*1024);
    convert_kernel<<<3072*1024/1024, 256>>>(Wqkv, 1, 3072*1024);
    convert_kernel<<<1024*1024/1024, 256>>>(Wout, 2, 1024*1024);

    mma_gemm<0><<<dim3(3072/256, 8192/128), 256, G_SMEM_B>>>(nullptr, nullptr);
    attn_mma<<<dim3(NTOK/128, HEADS, BATCH), 256, ATTN_SMEM>>>(ab);
    mma_gemm<1><<<dim3(1024/256, 8192/128), 256, G_SMEM_B>>>(bout, out);
}

// round 12
// speedup vs baseline: 1.7891x; 1.0568x over previous
#include <cuda_runtime.h>
#include <cuda_fp16.h>
#include <cstdint>

#define BATCH 8
#define HEADS 16
#define NTOK  1024
#define DHEAD 64
#define EMB   1024
#define KD    1024

// ---- scratch (allocation-free rule: __device__ globals) ----
// everything single fp16. layout [b,h,n,d] for q/k/v
__device__ __half g_q [BATCH*HEADS*NTOK*DHEAD];   // pre-scaled by 0.125
__device__ __half g_k [BATCH*HEADS*NTOK*DHEAD];
__device__ __half g_v [BATCH*HEADS*NTOK*DHEAD];

__device__ __half g_x [8192*1024];   // x fp16 (A side of QKV gemm)
__device__ __half g_wq[3072*1024];   // Wqkv fp16 (B side)
__device__ __half g_wo[1024*1024];   // Wout fp16
__device__ __half g_ao[8192*1024];   // attn-out fp16 (A side of out-proj)

// ---------------------------------------------------------------------------
__device__ __forceinline__ uint32_t smem_u32(const void* p) {
    return (uint32_t)__cvta_generic_to_shared(p);
}
__device__ __forceinline__ uint32_t pack2h(float x, float y) {
    __half2 t = __floats2half2_rn(x, y);
    return *reinterpret_cast<uint32_t*>(&t);
}
__device__ __forceinline__ void ldsm_x4(uint32_t* r, uint32_t addr) {
    asm volatile("ldmatrix.sync.aligned.m8n8.x4.shared.b16 {%0,%1,%2,%3},[%4];"
                 : "=r"(r[0]), "=r"(r[1]), "=r"(r[2]), "=r"(r[3]) : "r"(addr));
}
__device__ __forceinline__ void ldsm_x4_t(uint32_t* r, uint32_t addr) {
    asm volatile("ldmatrix.sync.aligned.m8n8.x4.trans.shared.b16 {%0,%1,%2,%3},[%4];"
                 : "=r"(r[0]), "=r"(r[1]), "=r"(r[2]), "=r"(r[3]) : "r"(addr));
}
__device__ __forceinline__ void mma_f16(float* c, const uint32_t* a, const uint32_t* b) {
    asm volatile("mma.sync.aligned.m16n8k16.row.col.f32.f16.f16.f32 "
                 "{%0,%1,%2,%3},{%4,%5,%6,%7},{%8,%9},{%0,%1,%2,%3};"
                 : "+f"(c[0]), "+f"(c[1]), "+f"(c[2]), "+f"(c[3])
                 : "r"(a[0]), "r"(a[1]), "r"(a[2]), "r"(a[3]), "r"(b[0]), "r"(b[1]));
}
__device__ __forceinline__ void cp16(uint32_t dst, const void* src) {
    asm volatile("cp.async.ca.shared.global [%0],[%1],16;" :: "r"(dst), "l"(src));
}
__device__ __forceinline__ void cp_commit() { asm volatile("cp.async.commit_group;"); }
__device__ __forceinline__ void cp_wait0() { asm volatile("cp.async.wait_group 0;"); }
__device__ __forceinline__ void cp_wait1() { asm volatile("cp.async.wait_group 1;"); }

// ---------------------------------------------------------------------------
// fp32 -> fp16 conversion. which 0: x; 1: Wqkv; 2: Wout
// ---------------------------------------------------------------------------
__global__ __launch_bounds__(256) void convert_kernel(const float* __restrict__ src,
                                                      int which, int n)
{
    int i = (blockIdx.x * 256 + threadIdx.x) * 4;
    if (i >= n) return;
    float4 v = *(const float4*)(src + i);
    uint2 p;
    p.x = pack2h(v.x, v.y);
    p.y = pack2h(v.z, v.w);
    if (which == 0)      *(uint2*)&g_x [i] = p;
    else if (which == 1) *(uint2*)&g_wq[i] = p;
    else                 *(uint2*)&g_wo[i] = p;
}

// ---------------------------------------------------------------------------
// Single-product fp16 HMMA GEMM: C[m,c] = A(m,:) . B(c,:)
// Block 128x128, 256 thr (8 warps as 2M x 4N), warp tile 64x32, K-step 32,
// cp.async double-buffered, 2 CTAs/SM.
// MODE 0: A=x, B=Wqkv -> q (scaled) / k / v fp16
// MODE 1: A=attn-out, B=Wout -> +bias -> C (fp32)
// ---------------------------------------------------------------------------
#define GSTR 40                               // smem row stride (elems)
#define PLB  (128 * GSTR * 2)                 // plane bytes (10240)
#define BUFB (2 * PLB)                        // A + B (20480)
#define G_SMEM_B (2 * BUFB)                   // 40960 (double-buffered)

template<int MODE>
__global__ __launch_bounds__(256, 2) void mma_gemm(const float* __restrict__ bias,
                                                   float* __restrict__ C)
{
    extern __shared__ __half gs[];

    const int t    = threadIdx.x;
    const int lane = t & 31;
    const int wid  = t >> 5;
    const int wm   = (wid & 1) << 6;       // 0 / 64
    const int wn   = (wid >> 1) << 5;      // 0..96
    const int m0   = blockIdx.y * 128;
    const int n0   = blockIdx.x * 128;

    const __half* Ap = (MODE == 0) ? g_x  : g_ao;
    const __half* Bp = (MODE == 0) ? g_wq : g_wo;

    const uint32_t s_base = smem_u32(gs);

#define G_LOAD(st, bf) do {                                                       \
    const int k0 = (st) * 32;                                                     \
    const uint32_t bo = s_base + (uint32_t)(bf) * BUFB;                           \
    _Pragma("unroll")                                                             \
    for (int u = 0; u < 2; u++) {          /* A/B: 128 rows x 4 chunks each */    \
        const int idx = t + u * 256;                                              \
        const int r = idx >> 2, c = (idx & 3) << 3;                               \
        const uint32_t so = (uint32_t)(r * GSTR + c) * 2;                         \
        cp16(bo + so,       Ap + (size_t)(m0 + r) * KD + k0 + c);                 \
        cp16(bo + PLB + so, Bp + (size_t)(n0 + r) * KD + k0 + c);                 \
    }                                                                             \
    cp_commit(); } while (0)

    const int a_r = wm + (lane & 15);
    const int a_c = (lane >> 4) << 3;
    const int b_r = wn + ((lane >> 4) << 3) + (lane & 7);
    const int b_c = ((lane >> 3) & 1) << 3;

    float acc[4][4][4];
    #pragma unroll
    for (int mt = 0; mt < 4; mt++)
        #pragma unroll
        for (int nt = 0; nt < 4; nt++)
            #pragma unroll
            for (int q = 0; q < 4; q++) acc[mt][nt][q] = 0.f;

    G_LOAD(0, 0);

    const int NSTEP = KD / 32;
    for (int st = 0; st < NSTEP; st++) {
        const int buf = st & 1;
        cp_wait0();
        __syncthreads();
        if (st + 1 < NSTEP) G_LOAD(st + 1, 1 - buf);

        const uint32_t bo = s_base + (uint32_t)buf * BUFB;
        #pragma unroll
        for (int kk = 0; kk < 32; kk += 16) {
            uint32_t ah[4][4], bf[2][4];
            #pragma unroll
            for (int mt = 0; mt < 4; mt++)
                ldsm_x4(ah[mt], bo + (uint32_t)(((a_r + mt * 16) * GSTR) + kk + a_c) * 2);
            #pragma unroll
            for (int pr = 0; pr < 2; pr++)
                ldsm_x4(bf[pr], bo + PLB
                    + (uint32_t)(((b_r + pr * 16) * GSTR) + kk + b_c) * 2);
            #pragma unroll
            for (int mt = 0; mt < 4; mt++)
                #pragma unroll
                for (int nt = 0; nt < 4; nt++) {
                    uint32_t* B0 = &bf[nt >> 1][(nt & 1) * 2];
                    mma_f16(acc[mt][nt], ah[mt], B0);
                }
        }
        __syncthreads();
    }

    // ---- epilogue ----
    const int part = (MODE == 0) ? (n0 >> 10) : 0;
    const int e0   = n0 & 1023;
    #pragma unroll
    for (int mt = 0; mt < 4; mt++) {
        #pragma unroll
        for (int half = 0; half < 2; half++) {
            const int m = m0 + wm + mt * 16 + (lane >> 2) + half * 8;
            if (MODE == 0) {
                const int bb = m >> 10, nn = m & 1023;
                #pragma unroll
                for (int nt = 0; nt < 4; nt++) {
                    const int e  = e0 + wn + nt * 8 + (lane & 3) * 2;
                    const int hh = e >> 6, d = e & 63;
                    const size_t off = ((size_t)((bb * HEADS + hh) * NTOK + nn) << 6) + d;
                    float vx = acc[mt][nt][half * 2], vy = acc[mt][nt][half * 2 + 1];
                    if (part == 0) {
                        *(uint32_t*)&g_q[off] = pack2h(vx * 0.125f, vy * 0.125f);
                    } else if (part == 1) {
                        *(uint32_t*)&g_k[off] = pack2h(vx, vy);
                    } else {
                        *(uint32_t*)&g_v[off] = pack2h(vx, vy);
                    }
                }
            } else {
                #pragma unroll
                for (int nt = 0; nt < 4; nt++) {
                    const int cg = n0 + wn + nt * 8 + (lane & 3) * 2;
                    const float2 b2 = *(const float2*)&bias[cg];
                    float2 v = make_float2(acc[mt][nt][half * 2] + b2.x,
                                           acc[mt][nt][half * 2 + 1] + b2.y);
                    *(float2*)&C[(size_t)m * EMB + cg] = v;
                }
            }
        }
    }
}

// ============================================================================
// Single-product fp16 flash attention. (unchanged from R11)
// Block = 128 queries (8 warps x m16), 16 key tiles of 64.
// smem: [2 bufs][K plane, V plane][64 rows][72 fp16] + bias[1024] f32
// ============================================================================
#define ASTR 72
#define PLNB (64 * ASTR * 2)                  // plane bytes (9216)
#define ATTN_SMEM (2 * 2 * PLNB + 1024 * 4)   // 40960

__global__ __launch_bounds__(256) void attn_mma(const float* __restrict__ biases)
{
    extern __shared__ __half smem[];
    float* s_bias = (float*)((char*)smem + 2 * 2 * PLNB);

    const int t = threadIdx.x, lane = t & 31, w = t >> 5;
    const int qt = blockIdx.x, h = blockIdx.y, b = blockIdx.z;
    const int bh = b * HEADS + h;
    const int q0 = qt * 128;
    const int rw = w * 16;

    for (int i = t; i < 1024; i += 256) s_bias[i] = biases[h * 1024 + i];

    // ---- Q fragment preload, staged through smem ----
    uint32_t qf[4][4];
    const uint32_t qAddr = smem_u32(smem) + ((rw + (lane & 15)) * ASTR + ((lane >> 4) << 3)) * 2;
    {
        const __half* qsrc = g_q + ((size_t)bh * NTOK + q0) * 64;
        #pragma unroll
        for (int u = 0; u < 4; u++) {
            const int id = t + u * 256, r = id >> 3, ch = (id & 7) * 8;
            cp16(smem_u32(smem + r * ASTR + ch), qsrc + (size_t)r * 64 + ch);
        }
        cp_commit(); cp_wait0(); __syncthreads();
        #pragma unroll
        for (int kk = 0; kk < 4; kk++) ldsm_x4(qf[kk], qAddr + kk * 32);
        __syncthreads();
    }

    float s[8][4], o[8][4];
    float m0 = -1e30f, m1 = -1e30f, l0 = 0.f, l1 = 0.f;
    #pragma unroll
    for (int f = 0; f < 8; f++)
        #pragma unroll
        for (int q = 0; q < 4; q++) o[f][q] = 0.f;

    const int r_row0 = q0 + rw + (lane >> 2);
    const int xq0 = r_row0 >> 5,       yq0 = r_row0 & 31;
    const int xq1 = (r_row0 + 8) >> 5, yq1 = (r_row0 + 8) & 31;

#define LOAD_TILE(kt, bf) do {                                                   \
    _Pragma("unroll")                                                            \
    for (int u = 0; u < 4; u++) {                                                \
        const int p = u >> 1;                                                    \
        const int id = t + u * 256;                                              \
        const int rr = (id >> 3) & 63, ch = (id & 7) * 8;                        \
        const __half* src = (p == 0) ? g_k : g_v;                                \
        cp16(smem_u32(smem + (((bf) * 2 + p) * 64 + rr) * ASTR + ch),            \
             src + ((size_t)bh * NTOK + (kt) * 64 + rr) * 64 + ch);              \
    }                                                                            \
    cp_commit(); } while (0)

    LOAD_TILE(0, 0);

    for (int kt = 0; kt < 16; kt++) {
        const int buf = kt & 1;
        if (kt < 15) { LOAD_TILE(kt + 1, 1 - buf); cp_wait1(); }
        else         { cp_wait0(); }
        __syncthreads();

        const uint32_t base = smem_u32(smem) + buf * 2 * PLNB;
        const uint32_t laddr = ((lane & 15) * ASTR + ((lane >> 4) << 3)) * 2;

        // ---- S = Q K^T ----
        #pragma unroll
        for (int f = 0; f < 8; f++)
            #pragma unroll
            for (int q = 0; q < 4; q++) s[f][q] = 0.f;

        #pragma unroll
        for (int kk = 0; kk < 4; kk++) {
            #pragma unroll
            for (int ng = 0; ng < 4; ng++) {
                uint32_t kf[4];
                ldsm_x4(kf, base + laddr + (ng * 16 * ASTR + kk * 16) * 2);
                uint32_t b0[2] = {kf[0], kf[2]}, b1[2] = {kf[1], kf[3]};
                mma_f16(s[2*ng],   qf[kk], b0);
                mma_f16(s[2*ng+1], qf[kk], b1);
            }
        }

        // ---- bias + online softmax ----
        float tm0 = -1e30f, tm1 = -1e30f;
        const int cb = kt * 64 + (lane & 3) * 2;
        #pragma unroll
        for (int f = 0; f < 8; f++) {
            const int c0 = cb + f * 8, c1 = c0 + 1;
            const int cx0 = c0 >> 5, cy0 = c0 & 31;
            const int cx1 = c1 >> 5, cy1 = c1 & 31;
            s[f][0] += s_bias[abs(xq0 - cx0) * 32 + abs(yq0 - cy0)];
            s[f][1] += s_bias[abs(xq0 - cx1) * 32 + abs(yq0 - cy1)];
            s[f][2] += s_bias[abs(xq1 - cx0) * 32 + abs(yq1 - cy0)];
            s[f][3] += s_bias[abs(xq1 - cx1) * 32 + abs(yq1 - cy1)];
            tm0 = fmaxf(tm0, fmaxf(s[f][0], s[f][1]));
            tm1 = fmaxf(tm1, fmaxf(s[f][2], s[f][3]));
        }
        tm0 = fmaxf(tm0, __shfl_xor_sync(0xffffffffu, tm0, 1));
        tm0 = fmaxf(tm0, __shfl_xor_sync(0xffffffffu, tm0, 2));
        tm1 = fmaxf(tm1, __shfl_xor_sync(0xffffffffu, tm1, 1));
        tm1 = fmaxf(tm1, __shfl_xor_sync(0xffffffffu, tm1, 2));

        const float mn0 = fmaxf(m0, tm0), mn1 = fmaxf(m1, tm1);
        const float fac0 = __expf(m0 - mn0), fac1 = __expf(m1 - mn1);
        m0 = mn0; m1 = mn1;
        l0 *= fac0; l1 *= fac1;
        #pragma unroll
        for (int f = 0; f < 8; f++) {
            s[f][0] = __expf(s[f][0] - m0); s[f][1] = __expf(s[f][1] - m0);
            s[f][2] = __expf(s[f][2] - m1); s[f][3] = __expf(s[f][3] - m1);
            l0 += s[f][0] + s[f][1];
            l1 += s[f][2] + s[f][3];
            o[f][0] *= fac0; o[f][1] *= fac0; o[f][2] *= fac1; o[f][3] *= fac1;
        }

        // ---- O += P V (P packed to fp16 in-register) ----
        const uint32_t vbase = base + PLNB;
        #pragma unroll
        for (int kk2 = 0; kk2 < 4; kk2++) {
            uint32_t ap[4];
            ap[0] = pack2h(s[2*kk2][0],   s[2*kk2][1]);
            ap[1] = pack2h(s[2*kk2][2],   s[2*kk2][3]);
            ap[2] = pack2h(s[2*kk2+1][0], s[2*kk2+1][1]);
            ap[3] = pack2h(s[2*kk2+1][2], s[2*kk2+1][3]);
            #pragma unroll
            for (int dg = 0; dg < 4; dg++) {
                const int nf = dg * 2;
                uint32_t vf[4];
                ldsm_x4_t(vf, vbase + laddr + (kk2 * 16 * ASTR + dg * 16) * 2);
                uint32_t b0[2] = {vf[0], vf[1]}, b1[2] = {vf[2], vf[3]};
                mma_f16(o[nf],   ap, b0);
                mma_f16(o[nf+1], ap, b1);
            }
        }
        __syncthreads();
    }

    // ---- epilogue: normalize, write attn-out fp16 ----
    l0 += __shfl_xor_sync(0xffffffffu, l0, 1);
    l0 += __shfl_xor_sync(0xffffffffu, l0, 2);
    l1 += __shfl_xor_sync(0xffffffffu, l1, 1);
    l1 += __shfl_xor_sync(0xffffffffu, l1, 2);
    const float inv0 = 1.0f / l0, inv1 = 1.0f / l1;

    const size_t rbase0 = ((size_t)(b * NTOK + r_row0)) * EMB + h * 64;
    const size_t rbase1 = rbase0 + (size_t)8 * EMB;
    #pragma unroll
    for (int f = 0; f < 8; f++) {
        const int d = f * 8 + (lane & 3) * 2;
        *(uint32_t*)&g_ao[rbase0 + d] = pack2h(o[f][0] * inv0, o[f][1] * inv0);
        *(uint32_t*)&g_ao[rbase1 + d] = pack2h(o[f][2] * inv1, o[f][3] * inv1);
    }
}

// ============================================================================
extern "C" void kernel_launch(void* const* d_in, const int* in_sizes, int n_in,
                              void* d_out, int out_size)
{
    const float* x     = (const float*)d_in[0];
    const float* Wqkv  = (const float*)d_in[1];
    const float* ab    = (const float*)d_in[2];
    // d_in[3] = bias_idxs : not needed (idx = |dx|*32 + |dy| analytically)
    const float* Wout  = (const float*)d_in[4];
    const float* bout  = (const float*)d_in[5];
    float* out = (float*)d_out;

    cudaFuncSetAttribute(attn_mma, cudaFuncAttributeMaxDynamicSharedMemorySize,
                         ATTN_SMEM);
    cudaFuncSetAttribute(mma_gemm<0>, cudaFuncAttributeMaxDynamicSharedMemorySize,
                         G_SMEM_B);
    cudaFuncSetAttribute(mma_gemm<1>, cudaFuncAttributeMaxDynamicSharedMemorySize,
                         G_SMEM_B);

    convert_kernel<<<8192*1024/1024, 256>>>(x,    0, 8192*1024);
    convert_kernel<<<3072*1024/1024, 256>>>(Wqkv, 1, 3072*1024);
    convert_kernel<<<1024*1024/1024, 256>>>(Wout, 2, 1024*1024);

    mma_gemm<0><<<dim3(3072/128, 8192/128), 256, G_SMEM_B>>>(nullptr, nullptr);
    attn_mma<<<dim3(NTOK/128, HEADS, BATCH), 256, ATTN_SMEM>>>(ab);
    mma_gemm<1><<<dim3(1024/128, 8192/128), 256, G_SMEM_B>>>(bout, out);
}

// round 14
// speedup vs baseline: 2.1638x; 1.2094x over previous
#include <cuda_runtime.h>
#include <cuda_fp16.h>
#include <cstdint>

#define BATCH 8
#define HEADS 16
#define NTOK  1024
#define DHEAD 64
#define EMB   1024
#define KD    1024

// ---- scratch (allocation-free rule: __device__ globals) ----
// everything single fp16. layout [b,h,n,d] for q/k/v
__device__ __half g_q [BATCH*HEADS*NTOK*DHEAD];   // pre-scaled by 0.125
__device__ __half g_k [BATCH*HEADS*NTOK*DHEAD];
__device__ __half g_v [BATCH*HEADS*NTOK*DHEAD];

__device__ __half g_x [8192*1024];   // x fp16 (A side of QKV gemm)
__device__ __half g_wq[3072*1024];   // Wqkv fp16 (B side)
__device__ __half g_wo[1024*1024];   // Wout fp16
__device__ __half g_ao[8192*1024];   // attn-out fp16 (A side of out-proj)

// ---------------------------------------------------------------------------
__device__ __forceinline__ uint32_t smem_u32(const void* p) {
    return (uint32_t)__cvta_generic_to_shared(p);
}
__device__ __forceinline__ uint32_t pack2h(float x, float y) {
    __half2 t = __floats2half2_rn(x, y);
    return *reinterpret_cast<uint32_t*>(&t);
}
__device__ __forceinline__ void ldsm_x4(uint32_t* r, uint32_t addr) {
    asm volatile("ldmatrix.sync.aligned.m8n8.x4.shared.b16 {%0,%1,%2,%3},[%4];"
                 : "=r"(r[0]), "=r"(r[1]), "=r"(r[2]), "=r"(r[3]) : "r"(addr));
}
__device__ __forceinline__ void ldsm_x4_t(uint32_t* r, uint32_t addr) {
    asm volatile("ldmatrix.sync.aligned.m8n8.x4.trans.shared.b16 {%0,%1,%2,%3},[%4];"
                 : "=r"(r[0]), "=r"(r[1]), "=r"(r[2]), "=r"(r[3]) : "r"(addr));
}
__device__ __forceinline__ void mma_f16(float* c, const uint32_t* a, const uint32_t* b) {
    asm volatile("mma.sync.aligned.m16n8k16.row.col.f32.f16.f16.f32 "
                 "{%0,%1,%2,%3},{%4,%5,%6,%7},{%8,%9},{%0,%1,%2,%3};"
                 : "+f"(c[0]), "+f"(c[1]), "+f"(c[2]), "+f"(c[3])
                 : "r"(a[0]), "r"(a[1]), "r"(a[2]), "r"(a[3]), "r"(b[0]), "r"(b[1]));
}
__device__ __forceinline__ void cp16(uint32_t dst, const void* src) {
    asm volatile("cp.async.ca.shared.global [%0],[%1],16;" :: "r"(dst), "l"(src));
}
__device__ __forceinline__ void cp_commit() { asm volatile("cp.async.commit_group;"); }
__device__ __forceinline__ void cp_wait0() { asm volatile("cp.async.wait_group 0;"); }
__device__ __forceinline__ void cp_wait1() { asm volatile("cp.async.wait_group 1;"); }

// ---------------------------------------------------------------------------
// fp32 -> fp16 conversion. which 0: x; 1: Wqkv; 2: Wout
// ---------------------------------------------------------------------------
__global__ __launch_bounds__(256) void convert_kernel(const float* __restrict__ src,
                                                      int which, int n)
{
    int i = (blockIdx.x * 256 + threadIdx.x) * 4;
    if (i >= n) return;
    float4 v = *(const float4*)(src + i);
    uint2 p;
    p.x = pack2h(v.x, v.y);
    p.y = pack2h(v.z, v.w);
    if (which == 0)      *(uint2*)&g_x [i] = p;
    else if (which == 1) *(uint2*)&g_wq[i] = p;
    else                 *(uint2*)&g_wo[i] = p;
}

// ---------------------------------------------------------------------------
// Single-product fp16 HMMA GEMM: C[m,c] = A(m,:) . B(c,:)
// Block 128x128, 256 thr (8 warps as 2M x 4N), warp tile 64x32, K-step 64,
// cp.async double-buffered, 2 CTAs/SM.  (K-step 64 halves barrier count.)
// MODE 0: A=x, B=Wqkv -> q (scaled) / k / v fp16
// MODE 1: A=attn-out, B=Wout -> +bias -> C (fp32)
// ---------------------------------------------------------------------------
#define GSTR 72                               // smem row stride (elems), 64+8
#define PLB  (128 * GSTR * 2)                 // plane bytes (18432)
#define BUFB (2 * PLB)                        // A + B (36864)
#define G_SMEM_B (2 * BUFB)                   // 73728 (double-buffered)

template<int MODE>
__global__ __launch_bounds__(256, 2) void mma_gemm(const float* __restrict__ bias,
                                                   float* __restrict__ C)
{
    extern __shared__ __half gs[];

    const int t    = threadIdx.x;
    const int lane = t & 31;
    const int wid  = t >> 5;
    const int wm   = (wid & 1) << 6;       // 0 / 64
    const int wn   = (wid >> 1) << 5;      // 0..96
    const int m0   = blockIdx.y * 128;
    const int n0   = blockIdx.x * 128;

    const __half* Ap = (MODE == 0) ? g_x  : g_ao;
    const __half* Bp = (MODE == 0) ? g_wq : g_wo;

    const uint32_t s_base = smem_u32(gs);

#define G_LOAD(st, bf) do {                                                       \
    const int k0 = (st) * 64;                                                     \
    const uint32_t bo = s_base + (uint32_t)(bf) * BUFB;                           \
    _Pragma("unroll")                                                             \
    for (int u = 0; u < 4; u++) {          /* A/B: 128 rows x 8 chunks each */    \
        const int idx = t + u * 256;                                              \
        const int r = idx >> 3, c = (idx & 7) << 3;                               \
        const uint32_t so = (uint32_t)(r * GSTR + c) * 2;                         \
        cp16(bo + so,       Ap + (size_t)(m0 + r) * KD + k0 + c);                 \
        cp16(bo + PLB + so, Bp + (size_t)(n0 + r) * KD + k0 + c);                 \
    }                                                                             \
    cp_commit(); } while (0)

    const int a_r = wm + (lane & 15);
    const int a_c = (lane >> 4) << 3;
    const int b_r = wn + ((lane >> 4) << 3) + (lane & 7);
    const int b_c = ((lane >> 3) & 1) << 3;

    float acc[4][4][4];
    #pragma unroll
    for (int mt = 0; mt < 4; mt++)
        #pragma unroll
        for (int nt = 0; nt < 4; nt++)
            #pragma unroll
            for (int q = 0; q < 4; q++) acc[mt][nt][q] = 0.f;

    G_LOAD(0, 0);

    const int NSTEP = KD / 64;             // 16
    for (int st = 0; st < NSTEP; st++) {
        const int buf = st & 1;
        cp_wait0();
        __syncthreads();
        if (st + 1 < NSTEP) G_LOAD(st + 1, 1 - buf);

        const uint32_t bo = s_base + (uint32_t)buf * BUFB;
        #pragma unroll
        for (int kk = 0; kk < 64; kk += 16) {
            uint32_t ah[4][4], bf[2][4];
            #pragma unroll
            for (int mt = 0; mt < 4; mt++)
                ldsm_x4(ah[mt], bo + (uint32_t)(((a_r + mt * 16) * GSTR) + kk + a_c) * 2);
            #pragma unroll
            for (int pr = 0; pr < 2; pr++)
                ldsm_x4(bf[pr], bo + PLB
                    + (uint32_t)(((b_r + pr * 16) * GSTR) + kk + b_c) * 2);
            #pragma unroll
            for (int mt = 0; mt < 4; mt++)
                #pragma unroll
                for (int nt = 0; nt < 4; nt++) {
                    uint32_t* B0 = &bf[nt >> 1][(nt & 1) * 2];
                    mma_f16(acc[mt][nt], ah[mt], B0);
                }
        }
        __syncthreads();
    }

    // ---- epilogue ----
    const int part = (MODE == 0) ? (n0 >> 10) : 0;
    const int e0   = n0 & 1023;
    #pragma unroll
    for (int mt = 0; mt < 4; mt++) {
        #pragma unroll
        for (int half = 0; half < 2; half++) {
            const int m = m0 + wm + mt * 16 + (lane >> 2) + half * 8;
            if (MODE == 0) {
                const int bb = m >> 10, nn = m & 1023;
                #pragma unroll
                for (int nt = 0; nt < 4; nt++) {
                    const int e  = e0 + wn + nt * 8 + (lane & 3) * 2;
                    const int hh = e >> 6, d = e & 63;
                    const size_t off = ((size_t)((bb * HEADS + hh) * NTOK + nn) << 6) + d;
                    float vx = acc[mt][nt][half * 2], vy = acc[mt][nt][half * 2 + 1];
                    if (part == 0) {
                        *(uint32_t*)&g_q[off] = pack2h(vx * 0.125f, vy * 0.125f);
                    } else if (part == 1) {
                        *(uint32_t*)&g_k[off] = pack2h(vx, vy);
                    } else {
                        *(uint32_t*)&g_v[off] = pack2h(vx, vy);
                    }
                }
            } else {
                #pragma unroll
                for (int nt = 0; nt < 4; nt++) {
                    const int cg = n0 + wn + nt * 8 + (lane & 3) * 2;
                    const float2 b2 = *(const float2*)&bias[cg];
                    float2 v = make_float2(acc[mt][nt][half * 2] + b2.x,
                                           acc[mt][nt][half * 2 + 1] + b2.y);
                    *(float2*)&C[(size_t)m * EMB + cg] = v;
                }
            }
        }
    }
}

// ============================================================================
// Single-product fp16 flash attention; now 2 CTAs/SM.
// Block = 128 queries (8 warps x m16), 16 key tiles of 64.
// smem: [2 bufs][K plane, V plane][64 rows][72 fp16] + bias[1024] f32
// ============================================================================
#define ASTR 72
#define PLNB (64 * ASTR * 2)                  // plane bytes (9216)
#define ATTN_SMEM (2 * 2 * PLNB + 1024 * 4)   // 40960

__global__ __launch_bounds__(256, 2) void attn_mma(const float* __restrict__ biases)
{
    extern __shared__ __half smem[];
    float* s_bias = (float*)((char*)smem + 2 * 2 * PLNB);

    const int t = threadIdx.x, lane = t & 31, w = t >> 5;
    const int qt = blockIdx.x, h = blockIdx.y, b = blockIdx.z;
    const int bh = b * HEADS + h;
    const int q0 = qt * 128;
    const int rw = w * 16;

    for (int i = t; i < 1024; i += 256) s_bias[i] = biases[h * 1024 + i];

    // ---- Q fragment preload, staged through smem ----
    uint32_t qf[4][4];
    const uint32_t qAddr = smem_u32(smem) + ((rw + (lane & 15)) * ASTR + ((lane >> 4) << 3)) * 2;
    {
        const __half* qsrc = g_q + ((size_t)bh * NTOK + q0) * 64;
        #pragma unroll
        for (int u = 0; u < 4; u++) {
            const int id = t + u * 256, r = id >> 3, ch = (id & 7) * 8;
            cp16(smem_u32(smem + r * ASTR + ch), qsrc + (size_t)r * 64 + ch);
        }
        cp_commit(); cp_wait0(); __syncthreads();
        #pragma unroll
        for (int kk = 0; kk < 4; kk++) ldsm_x4(qf[kk], qAddr + kk * 32);
        __syncthreads();
    }

    float s[8][4], o[8][4];
    float m0 = -1e30f, m1 = -1e30f, l0 = 0.f, l1 = 0.f;
    #pragma unroll
    for (int f = 0; f < 8; f++)
        #pragma unroll
        for (int q = 0; q < 4; q++) o[f][q] = 0.f;

    const int r_row0 = q0 + rw + (lane >> 2);
    const int xq0 = r_row0 >> 5,       yq0 = r_row0 & 31;
    const int xq1 = (r_row0 + 8) >> 5, yq1 = (r_row0 + 8) & 31;

#define LOAD_TILE(kt, bf) do {                                                   \
    _Pragma("unroll")                                                            \
    for (int u = 0; u < 4; u++) {                                                \
        const int p = u >> 1;                                                    \
        const int id = t + u * 256;                                              \
        const int rr = (id >> 3) & 63, ch = (id & 7) * 8;                        \
        const __half* src = (p == 0) ? g_k : g_v;                                \
        cp16(smem_u32(smem + (((bf) * 2 + p) * 64 + rr) * ASTR + ch),            \
             src + ((size_t)bh * NTOK + (kt) * 64 + rr) * 64 + ch);              \
    }                                                                            \
    cp_commit(); } while (0)

    LOAD_TILE(0, 0);

    for (int kt = 0; kt < 16; kt++) {
        const int buf = kt & 1;
        if (kt < 15) { LOAD_TILE(kt + 1, 1 - buf); cp_wait1(); }
        else         { cp_wait0(); }
        __syncthreads();

        const uint32_t base = smem_u32(smem) + buf * 2 * PLNB;
        const uint32_t laddr = ((lane & 15) * ASTR + ((lane >> 4) << 3)) * 2;

        // ---- S = Q K^T ----
        #pragma unroll
        for (int f = 0; f < 8; f++)
            #pragma unroll
            for (int q = 0; q < 4; q++) s[f][q] = 0.f;

        #pragma unroll
        for (int kk = 0; kk < 4; kk++) {
            #pragma unroll
            for (int ng = 0; ng < 4; ng++) {
                uint32_t kf[4];
                ldsm_x4(kf, base + laddr + (ng * 16 * ASTR + kk * 16) * 2);
                uint32_t b0[2] = {kf[0], kf[2]}, b1[2] = {kf[1], kf[3]};
                mma_f16(s[2*ng],   qf[kk], b0);
                mma_f16(s[2*ng+1], qf[kk], b1);
            }
        }

        // ---- bias + online softmax ----
        float tm0 = -1e30f, tm1 = -1e30f;
        const int cb = kt * 64 + (lane & 3) * 2;
        #pragma unroll
        for (int f = 0; f < 8; f++) {
            const int c0 = cb + f * 8, c1 = c0 + 1;
            const int cx0 = c0 >> 5, cy0 = c0 & 31;
            const int cx1 = c1 >> 5, cy1 = c1 & 31;
            s[f][0] += s_bias[abs(xq0 - cx0) * 32 + abs(yq0 - cy0)];
            s[f][1] += s_bias[abs(xq0 - cx1) * 32 + abs(yq0 - cy1)];
            s[f][2] += s_bias[abs(xq1 - cx0) * 32 + abs(yq1 - cy0)];
            s[f][3] += s_bias[abs(xq1 - cx1) * 32 + abs(yq1 - cy1)];
            tm0 = fmaxf(tm0, fmaxf(s[f][0], s[f][1]));
            tm1 = fmaxf(tm1, fmaxf(s[f][2], s[f][3]));
        }
        tm0 = fmaxf(tm0, __shfl_xor_sync(0xffffffffu, tm0, 1));
        tm0 = fmaxf(tm0, __shfl_xor_sync(0xffffffffu, tm0, 2));
        tm1 = fmaxf(tm1, __shfl_xor_sync(0xffffffffu, tm1, 1));
        tm1 = fmaxf(tm1, __shfl_xor_sync(0xffffffffu, tm1, 2));

        const float mn0 = fmaxf(m0, tm0), mn1 = fmaxf(m1, tm1);
        const float fac0 = __expf(m0 - mn0), fac1 = __expf(m1 - mn1);
        m0 = mn0; m1 = mn1;
        l0 *= fac0; l1 *= fac1;
        #pragma unroll
        for (int f = 0; f < 8; f++) {
            s[f][0] = __expf(s[f][0] - m0); s[f][1] = __expf(s[f][1] - m0);
            s[f][2] = __expf(s[f][2] - m1); s[f][3] = __expf(s[f][3] - m1);
            l0 += s[f][0] + s[f][1];
            l1 += s[f][2] + s[f][3];
            o[f][0] *= fac0; o[f][1] *= fac0; o[f][2] *= fac1; o[f][3] *= fac1;
        }

        // ---- O += P V (P packed to fp16 in-register) ----
        const uint32_t vbase = base + PLNB;
        #pragma unroll
        for (int kk2 = 0; kk2 < 4; kk2++) {
            uint32_t ap[4];
            ap[0] = pack2h(s[2*kk2][0],   s[2*kk2][1]);
            ap[1] = pack2h(s[2*kk2][2],   s[2*kk2][3]);
            ap[2] = pack2h(s[2*kk2+1][0], s[2*kk2+1][1]);
            ap[3] = pack2h(s[2*kk2+1][2], s[2*kk2+1][3]);
            #pragma unroll
            for (int dg = 0; dg < 4; dg++) {
                const int nf = dg * 2;
                uint32_t vf[4];
                ldsm_x4_t(vf, vbase + laddr + (kk2 * 16 * ASTR + dg * 16) * 2);
                uint32_t b0[2] = {vf[0], vf[1]}, b1[2] = {vf[2], vf[3]};
                mma_f16(o[nf],   ap, b0);
                mma_f16(o[nf+1], ap, b1);
            }
        }
        __syncthreads();
    }

    // ---- epilogue: normalize, write attn-out fp16 ----
    l0 += __shfl_xor_sync(0xffffffffu, l0, 1);
    l0 += __shfl_xor_sync(0xffffffffu, l0, 2);
    l1 += __shfl_xor_sync(0xffffffffu, l1, 1);
    l1 += __shfl_xor_sync(0xffffffffu, l1, 2);
    const float inv0 = 1.0f / l0, inv1 = 1.0f / l1;

    const size_t rbase0 = ((size_t)(b * NTOK + r_row0)) * EMB + h * 64;
    const size_t rbase1 = rbase0 + (size_t)8 * EMB;
    #pragma unroll
    for (int f = 0; f < 8; f++) {
        const int d = f * 8 + (lane & 3) * 2;
        *(uint32_t*)&g_ao[rbase0 + d] = pack2h(o[f][0] * inv0, o[f][1] * inv0);
        *(uint32_t*)&g_ao[rbase1 + d] = pack2h(o[f][2] * inv1, o[f][3] * inv1);
    }
}

// ============================================================================
extern "C" void kernel_launch(void* const* d_in, const int* in_sizes, int n_in,
                              void* d_out, int out_size)
{
    const float* x     = (const float*)d_in[0];
    const float* Wqkv  = (const float*)d_in[1];
    const float* ab    = (const float*)d_in[2];
    // d_in[3] = bias_idxs : not needed (idx = |dx|*32 + |dy| analytically)
    const float* Wout  = (const float*)d_in[4];
    const float* bout  = (const float*)d_in[5];
    float* out = (float*)d_out;

    cudaFuncSetAttribute(attn_mma, cudaFuncAttributeMaxDynamicSharedMemorySize,
                         ATTN_SMEM);
    cudaFuncSetAttribute(mma_gemm<0>, cudaFuncAttributeMaxDynamicSharedMemorySize,
                         G_SMEM_B);
    cudaFuncSetAttribute(mma_gemm<1>, cudaFuncAttributeMaxDynamicSharedMemorySize,
                         G_SMEM_B);

    convert_kernel<<<8192*1024/1024, 256>>>(x,    0, 8192*1024);
    convert_kernel<<<3072*1024/1024, 256>>>(Wqkv, 1, 3072*1024);
    convert_kernel<<<1024*1024/1024, 256>>>(Wout, 2, 1024*1024);

    mma_gemm<0><<<dim3(3072/128, 8192/128), 256, G_SMEM_B>>>(nullptr, nullptr);
    attn_mma<<<dim3(NTOK/128, HEADS, BATCH), 256, ATTN_SMEM>>>(ab);
    mma_gemm<1><<<dim3(1024/128, 8192/128), 256, G_SMEM_B>>>(bout, out);
}